// round 8
// baseline (speedup 1.0000x reference)
#include <cuda_runtime.h>
#include <cuda_fp16.h>

#define BATCH 32
#define H 512
#define W 512
#define NPIX (H*W)
#define NITER 10

#define TX 128
#define TY 64
#define NT 512

// Packed-pair buffers: entry(k,c) = (row y0+k, row y0+k+32) at col x0+c,
// k in [-10,42), c in [-10,138), stored at [(k+10)*SS + (c+10)].
#define SS 149
#define RMAX 52
#define BUF_H2 (RMAX * SS)
#define SMEM_BYTES (2 * BUF_H2 * (int)sizeof(__half2))

__device__ int g_t[BATCH];

// Decide whether the t buffer is int32 or int64 (reference does astype(int64),
// but JAX default x64=False makes it int32).
__global__ void prep_t(const int* __restrict__ t32) {
    __shared__ int is64;
    if (threadIdx.x == 0) {
        int ok = 1;
        for (int i = 0; i < BATCH; i++)
            ok &= (t32[2 * i + 1] == 0) && ((unsigned)t32[2 * i] < 16u);
        is64 = ok;
    }
    __syncthreads();
    int b = threadIdx.x;
    if (b < BATCH) {
        int v = is64 ? t32[2 * b] : t32[b];
        g_t[b] = max(0, min(NITER, v));
    }
}

__device__ __forceinline__ void sort3h(__half2& a, __half2& b, __half2& c) {
    __half2 t;
    t = __hmin2(a, b); b = __hmax2(a, b); a = t;
    t = __hmin2(b, c); c = __hmax2(b, c); b = t;
    t = __hmin2(a, b); b = __hmax2(a, b); a = t;
}
__device__ __forceinline__ __half2 med3h(__half2 a, __half2 b, __half2 c) {
    return __hmin2(__hmax2(a, b), __hmax2(__hmin2(a, b), c));
}

// 9 packed medians from a 3-row strip; emit(i, v) consumes each result.
template<class F>
__device__ __forceinline__ void med_strip9(const __half2* __restrict__ r0,
                                           const __half2* __restrict__ r1,
                                           const __half2* __restrict__ r2,
                                           F&& emit) {
    __half2 lA = r0[0], mA = r1[0], hA = r2[0]; sort3h(lA, mA, hA);
    __half2 lB = r0[1], mB = r1[1], hB = r2[1]; sort3h(lB, mB, hB);
#pragma unroll
    for (int i = 0; i < 9; i++) {
        __half2 lC = r0[2 + i], mC = r1[2 + i], hC = r2[2 + i];
        sort3h(lC, mC, hC);
        __half2 lo = __hmax2(__hmax2(lA, lB), lC);
        __half2 hi = __hmin2(__hmin2(hA, hB), hC);
        __half2 md = med3h(mA, mB, mC);
        emit(i, med3h(lo, md, hi));
        lA = lB; mA = mB; hA = hB;
        lB = lC; mB = mC; hB = hC;
    }
}

// All n = g_t[b] median steps for one 128x64 tile, in shared memory, ping-pong.
__global__ __launch_bounds__(NT, 3) void medianAll(const float* __restrict__ x,
                                                   float* __restrict__ out) {
    const int b = blockIdx.z;
    const int n = g_t[b];
    const int x0 = blockIdx.x * TX;
    const int y0 = blockIdx.y * TY;
    const float* __restrict__ src = x + (size_t)b * NPIX;
    float* __restrict__ dst = out + (size_t)b * NPIX;
    const int t = threadIdx.x;

    if (n == 0) {           // identity: copy tile
        for (int idx = t; idx < TY * (TX / 4); idx += NT) {
            int r = idx >> 5, cq = idx & 31;
            ((float4*)(dst + (size_t)(y0 + r) * W + x0))[cq] =
                ((const float4*)(src + (size_t)(y0 + r) * W + x0))[cq];
        }
        return;
    }

    extern __shared__ __half2 sm[];
    __half2* const P0 = sm;
    __half2* const P1 = sm + BUF_H2;

    const bool yTop = (y0 == 0), yBot = (y0 + TY == H);
    const bool xL = (x0 == 0), xR = (x0 + TX == W);
    const bool border = yTop | yBot | xL | xR;

    // ---- Load packed pairs with n-deep halo into P0 (level-0 edge clamp).
    const int rows_in = 32 + 2 * n, cols_in = 128 + 2 * n;
    if (!border) {
        for (int idx = t; idx < rows_in * cols_in; idx += NT) {
            int a = idx / cols_in, c = idx - a * cols_in;
            int k = a - n, cc = c - n;
            const float* p = src + (size_t)(y0 + k) * W + (x0 + cc);
            P0[(k + 10) * SS + (cc + 10)] = __floats2half2_rn(p[0], p[32 * W]);
        }
    } else {
        for (int idx = t; idx < rows_in * cols_in; idx += NT) {
            int a = idx / cols_in, c = idx - a * cols_in;
            int k = a - n, cc = c - n;
            int gy0 = min(H - 1, max(0, y0 + k));
            int gy1 = min(H - 1, y0 + k + 32);
            int gx = min(W - 1, max(0, x0 + cc));
            P0[(k + 10) * SS + (cc + 10)] =
                __floats2half2_rn(src[gy0 * W + gx], src[gy1 * W + gx]);
        }
    }
    __syncthreads();

    for (int d = 0; d < n; d++) {
        const __half2* __restrict__ pin = (d & 1) ? P1 : P0;
        __half2* __restrict__ pout = (d & 1) ? P0 : P1;
        const int g = n - d - 1;              // output halo
        const int bases = 32 + 2 * g;
        const int cols = 128 + 2 * g;
        const int strips = (cols + 8) / 9;
        const int total = bases * strips;
        const bool last = (d == n - 1);

        for (int item = t; item < total; item += NT) {
            const int kb = item % bases;      // consecutive lanes -> consecutive
            const int st = item / bases;      // bases: conflict-free LDS banks
            const int k = kb - g;
            const int c1 = -g + min(9 * st, cols - 9);
            const __half2* p = pin + (k - 1 + 10) * SS + (c1 - 1 + 10);
            if (!last) {
                __half2* q = pout + (k + 10) * SS + (c1 + 10);
                med_strip9(p, p + SS, p + 2 * SS,
                           [&](int i, __half2 v) { q[i] = v; });
            } else {
                float* o0 = dst + (size_t)(y0 + k) * W + (x0 + c1);
                med_strip9(p, p + SS, p + 2 * SS, [&](int i, __half2 v) {
                    o0[i] = __low2float(v);
                    o0[i + 32 * W] = __high2float(v);
                });
            }
        }

        if (!last) {
            __syncthreads();
            // ---- Mid-level edge repair on pout (border tiles only):
            // out-of-image halo entries := clamped copy of edge values.
            if (border & (g > 0)) {
                const int clo = xL ? 0 : -g;
                const int chi = xR ? 127 : 127 + g;
                const int cw = chi - clo + 1;
                if (yTop) {                 // bases <0: low lane := mid row 0
                    for (int idx = t; idx < g * cw; idx += NT) {
                        int kk = -g + idx / cw, c = clo + idx % cw;
                        __half2* e = pout + (kk + 10) * SS + (c + 10);
                        __half2 s0 = pout[10 * SS + (c + 10)];
                        *e = __halves2half2(__low2half(s0), __high2half(*e));
                    }
                }
                if (yBot) {                 // bases >=32: high lane := mid row 63
                    for (int idx = t; idx < g * cw; idx += NT) {
                        int kk = 32 + idx / cw, c = clo + idx % cw;
                        __half2* e = pout + (kk + 10) * SS + (c + 10);
                        __half2 s1 = pout[41 * SS + (c + 10)];
                        *e = __halves2half2(__low2half(*e), __high2half(s1));
                    }
                }
                if (xL | xR) {              // cols outside := col 0 / 127
                    const int kcnt = 32 + 2 * g;
                    const int sides = (xL && xR) ? 2 : 1;
                    for (int idx = t; idx < sides * g * kcnt; idx += NT) {
                        int side = xL ? (idx >= g * kcnt) : 1;
                        int r = xL ? (idx - side * g * kcnt) : idx;
                        int kk = -g + r % kcnt;
                        int cc = r / kcnt;
                        int ct = side ? (128 + cc) : (-1 - cc);
                        int cs = side ? 127 : 0;
                        __half2 s = pout[(kk + 10) * SS + (cs + 10)];
                        __half lo = __low2half(s), hi = __high2half(s);
                        if (yTop && kk < 0)
                            lo = __low2half(pout[10 * SS + (cs + 10)]);
                        if (yBot && kk >= 32)
                            hi = __high2half(pout[41 * SS + (cs + 10)]);
                        pout[(kk + 10) * SS + (ct + 10)] = __halves2half2(lo, hi);
                    }
                }
            }
            __syncthreads();
        }
    }
}

extern "C" void kernel_launch(void* const* d_in, const int* in_sizes, int n_in,
                              void* d_out, int out_size)
{
    const float* x = (const float*)d_in[0];
    const int* traw = (const int*)d_in[1];
    float* out = (float*)d_out;

    cudaFuncSetAttribute(medianAll, cudaFuncAttributeMaxDynamicSharedMemorySize,
                         SMEM_BYTES);
    prep_t<<<1, 32>>>(traw);
    medianAll<<<dim3(W / TX, H / TY, BATCH), NT, SMEM_BYTES>>>(x, out);
}

// round 9
// speedup vs baseline: 1.4871x; 1.4871x over previous
#include <cuda_runtime.h>
#include <cuda_fp16.h>

#define BATCH 32
#define H 512
#define W 512
#define NPIX (H*W)
#define NITER 10

#define TX 128
#define TY 64
#define NT 512

// Packed-pair buffers: entry(k,c) = (row y0+k, row y0+k+32) at col x0+c,
// k in [-10,42), c in [-10,138), stored at [(k+10)*SS + (c+10)].
#define SS 149
#define RMAX 52
#define BUF_H2 (RMAX * SS)
#define SMEM_BYTES (2 * BUF_H2 * (int)sizeof(__half2))

__device__ int g_t[BATCH];

// Decide whether the t buffer is int32 or int64 (reference does astype(int64),
// but JAX default x64=False makes it int32).
__global__ void prep_t(const int* __restrict__ t32) {
    __shared__ int is64;
    if (threadIdx.x == 0) {
        int ok = 1;
        for (int i = 0; i < BATCH; i++)
            ok &= (t32[2 * i + 1] == 0) && ((unsigned)t32[2 * i] < 16u);
        is64 = ok;
    }
    __syncthreads();
    int b = threadIdx.x;
    if (b < BATCH) {
        int v = is64 ? t32[2 * b] : t32[b];
        g_t[b] = max(0, min(NITER, v));
    }
}

__device__ __forceinline__ void sort3h(__half2& a, __half2& b, __half2& c) {
    __half2 t;
    t = __hmin2(a, b); b = __hmax2(a, b); a = t;
    t = __hmin2(b, c); c = __hmax2(b, c); b = t;
    t = __hmin2(a, b); b = __hmax2(a, b); a = t;
}
__device__ __forceinline__ __half2 med3h(__half2 a, __half2 b, __half2 c) {
    return __hmin2(__hmax2(a, b), __hmax2(__hmin2(a, b), c));
}

// 9 packed medians from a 3-row strip, written to q[0..8].
__device__ __forceinline__ void med_strip9(const __half2* __restrict__ r0,
                                           const __half2* __restrict__ r1,
                                           const __half2* __restrict__ r2,
                                           __half2* __restrict__ q) {
    __half2 lA = r0[0], mA = r1[0], hA = r2[0]; sort3h(lA, mA, hA);
    __half2 lB = r0[1], mB = r1[1], hB = r2[1]; sort3h(lB, mB, hB);
#pragma unroll
    for (int i = 0; i < 9; i++) {
        __half2 lC = r0[2 + i], mC = r1[2 + i], hC = r2[2 + i];
        sort3h(lC, mC, hC);
        __half2 lo = __hmax2(__hmax2(lA, lB), lC);
        __half2 hi = __hmin2(__hmin2(hA, hB), hC);
        __half2 md = med3h(mA, mB, mC);
        q[i] = med3h(lo, md, hi);
        lA = lB; mA = mB; hA = hB;
        lB = lC; mB = mC; hB = hC;
    }
}

// All n = g_t[b] median steps for one 128x64 tile, in shared memory, ping-pong.
__global__ __launch_bounds__(NT, 3) void medianAll(const float* __restrict__ x,
                                                   float* __restrict__ out) {
    const int b = blockIdx.z;
    const int n = g_t[b];
    const int x0 = blockIdx.x * TX;
    const int y0 = blockIdx.y * TY;
    const float* __restrict__ src = x + (size_t)b * NPIX;
    float* __restrict__ dst = out + (size_t)b * NPIX;
    const int t = threadIdx.x;

    if (n == 0) {           // identity: copy tile
        for (int idx = t; idx < TY * (TX / 4); idx += NT) {
            int r = idx >> 5, cq = idx & 31;
            ((float4*)(dst + (size_t)(y0 + r) * W + x0))[cq] =
                ((const float4*)(src + (size_t)(y0 + r) * W + x0))[cq];
        }
        return;
    }

    extern __shared__ __half2 sm[];
    __half2* const P0 = sm;
    __half2* const P1 = sm + BUF_H2;

    const bool yTop = (y0 == 0), yBot = (y0 + TY == H);
    const bool xL = (x0 == 0), xR = (x0 + TX == W);
    const bool border = yTop | yBot | xL | xR;

    // ---- Load packed pairs with n-deep halo into P0 (level-0 edge clamp).
    const int rows_in = 32 + 2 * n, cols_in = 128 + 2 * n;
    if (!border) {
        for (int idx = t; idx < rows_in * cols_in; idx += NT) {
            int a = idx / cols_in, c = idx - a * cols_in;
            int k = a - n, cc = c - n;
            const float* p = src + (size_t)(y0 + k) * W + (x0 + cc);
            P0[(k + 10) * SS + (cc + 10)] = __floats2half2_rn(p[0], p[32 * W]);
        }
    } else {
        for (int idx = t; idx < rows_in * cols_in; idx += NT) {
            int a = idx / cols_in, c = idx - a * cols_in;
            int k = a - n, cc = c - n;
            int gy0 = min(H - 1, max(0, y0 + k));
            int gy1 = min(H - 1, y0 + k + 32);
            int gx = min(W - 1, max(0, x0 + cc));
            P0[(k + 10) * SS + (cc + 10)] =
                __floats2half2_rn(src[gy0 * W + gx], src[gy1 * W + gx]);
        }
    }
    __syncthreads();

    for (int d = 0; d < n; d++) {
        const __half2* __restrict__ pin = (d & 1) ? P1 : P0;
        __half2* __restrict__ pout = (d & 1) ? P0 : P1;
        const int g = n - d - 1;              // output halo
        const int bases = 32 + 2 * g;
        const int cols = 128 + 2 * g;
        const int strips = (cols + 8) / 9;
        const int total = bases * strips;

        for (int item = t; item < total; item += NT) {
            const int kb = item % bases;      // consecutive lanes -> consecutive
            const int st = item / bases;      // bases: conflict-free LDS/STS banks
            const int k = kb - g;
            const int c1 = -g + min(9 * st, cols - 9);
            const __half2* p = pin + (k - 1 + 10) * SS + (c1 - 1 + 10);
            med_strip9(p, p + SS, p + 2 * SS, pout + (k + 10) * SS + (c1 + 10));
        }
        __syncthreads();

        // ---- Mid-level edge repair on pout (border tiles only):
        // out-of-image halo entries := clamped copy of edge values.
        if (border && g > 0) {
            const int clo = xL ? 0 : -g;
            const int chi = xR ? 127 : 127 + g;
            const int cw = chi - clo + 1;
            if (yTop) {                 // bases <0: low lane := mid row 0
                for (int idx = t; idx < g * cw; idx += NT) {
                    int kk = -g + idx / cw, c = clo + idx % cw;
                    __half2* e = pout + (kk + 10) * SS + (c + 10);
                    __half2 s0 = pout[10 * SS + (c + 10)];
                    *e = __halves2half2(__low2half(s0), __high2half(*e));
                }
            }
            if (yBot) {                 // bases >=32: high lane := mid row 63
                for (int idx = t; idx < g * cw; idx += NT) {
                    int kk = 32 + idx / cw, c = clo + idx % cw;
                    __half2* e = pout + (kk + 10) * SS + (c + 10);
                    __half2 s1 = pout[41 * SS + (c + 10)];
                    *e = __halves2half2(__low2half(*e), __high2half(s1));
                }
            }
            if (xL | xR) {              // cols outside := col 0 / 127
                const int kcnt = 32 + 2 * g;
                const int sides = (xL && xR) ? 2 : 1;
                for (int idx = t; idx < sides * g * kcnt; idx += NT) {
                    int side = xL ? (idx >= g * kcnt) : 1;
                    int r = xL ? (idx - side * g * kcnt) : idx;
                    int kk = -g + r % kcnt;
                    int cc = r / kcnt;
                    int ct = side ? (128 + cc) : (-1 - cc);
                    int cs = side ? 127 : 0;
                    __half2 s = pout[(kk + 10) * SS + (cs + 10)];
                    __half lo = __low2half(s), hi = __high2half(s);
                    if (yTop && kk < 0)
                        lo = __low2half(pout[10 * SS + (cs + 10)]);
                    if (yBot && kk >= 32)
                        hi = __high2half(pout[41 * SS + (cs + 10)]);
                    pout[(kk + 10) * SS + (ct + 10)] = __halves2half2(lo, hi);
                }
            }
            __syncthreads();
        }
    }

    // ---- Coalesced fp32 epilogue from the final-parity buffer.
    const __half2* __restrict__ F = (n & 1) ? P1 : P0;
    for (int idx = t; idx < TY * (TX / 4); idx += NT) {
        int y = idx >> 5, cq = idx & 31;
        const __half2* e = F + ((y & 31) + 10) * SS + (4 * cq + 10);
        float4 v;
        if (y >> 5)
            v = make_float4(__high2float(e[0]), __high2float(e[1]),
                            __high2float(e[2]), __high2float(e[3]));
        else
            v = make_float4(__low2float(e[0]), __low2float(e[1]),
                            __low2float(e[2]), __low2float(e[3]));
        ((float4*)(dst + (size_t)(y0 + y) * W + x0))[cq] = v;
    }
}

extern "C" void kernel_launch(void* const* d_in, const int* in_sizes, int n_in,
                              void* d_out, int out_size)
{
    const float* x = (const float*)d_in[0];
    const int* traw = (const int*)d_in[1];
    float* out = (float*)d_out;

    cudaFuncSetAttribute(medianAll, cudaFuncAttributeMaxDynamicSharedMemorySize,
                         SMEM_BYTES);
    prep_t<<<1, 32>>>(traw);
    medianAll<<<dim3(W / TX, H / TY, BATCH), NT, SMEM_BYTES>>>(x, out);
}